// round 3
// baseline (speedup 1.0000x reference)
#include <cuda_runtime.h>
#include <cuda_bf16.h>
#include <cstdint>

#define D_MODEL 4096
#define N_TOK   8192

__device__ __nv_bfloat16 g_ahi[(size_t)N_TOK * D_MODEL];
__device__ __nv_bfloat16 g_alo[(size_t)N_TOK * D_MODEL];
__device__ __nv_bfloat16 g_wq [(size_t)D_MODEL * D_MODEL];
__device__ float         g_y  [(size_t)N_TOK * D_MODEL];
__device__ double        g_part[1024];
__device__ float         g_scale;

static __device__ __forceinline__ uint32_t smem_u32(const void* p) {
    uint32_t r;
    asm("{ .reg .u64 t; cvta.to.shared.u64 t, %1; cvt.u32.u64 %0, t; }" : "=r"(r) : "l"(p));
    return r;
}
#define CP16(dst, ptr) do { \
    unsigned long long g_ = __cvta_generic_to_global((const void*)(ptr)); \
    asm volatile("cp.async.cg.shared.global [%0], [%1], 16;" :: "r"(dst), "l"(g_)); } while (0)
#define CP_COMMIT() asm volatile("cp.async.commit_group;")
#define CP_WAIT(n)  asm volatile("cp.async.wait_group %0;" :: "n"(n))

// ---- kernel 1: mean(|W|) in fp64, deterministic ----
__global__ void __launch_bounds__(256) absmean_part(const float* __restrict__ w) {
    double s = 0.0;
    for (int i = blockIdx.x * 256 + threadIdx.x; i < D_MODEL * D_MODEL; i += 1024 * 256)
        s += (double)fabsf(w[i]);
    __shared__ double rd[256];
    rd[threadIdx.x] = s; __syncthreads();
    for (int o = 128; o > 0; o >>= 1) { if (threadIdx.x < o) rd[threadIdx.x] += rd[threadIdx.x + o]; __syncthreads(); }
    if (threadIdx.x == 0) g_part[blockIdx.x] = rd[0];
}
__global__ void __launch_bounds__(256) absmean_fin() {
    int t = threadIdx.x;
    __shared__ double rd[256];
    rd[t] = g_part[t] + g_part[t + 256] + g_part[t + 512] + g_part[t + 768];
    __syncthreads();
    for (int o = 128; o > 0; o >>= 1) { if (t < o) rd[t] += rd[t + o]; __syncthreads(); }
    if (t == 0) g_scale = (float)(rd[0] / 16777216.0 + 1e-8);
}

// ---- kernel 2: ternarize -> bf16 ----
__global__ void __launch_bounds__(256) quant_kernel(const float* __restrict__ w) {
    const float s = g_scale;
    for (int i = blockIdx.x * 256 + threadIdx.x; i < (D_MODEL * D_MODEL) / 4; i += 2048 * 256) {
        float4 wv = ((const float4*)w)[i];
        __nv_bfloat162 a, b;
        a.x = __float2bfloat16(fminf(fmaxf(rintf(wv.x / s), -1.f), 1.f));
        a.y = __float2bfloat16(fminf(fmaxf(rintf(wv.y / s), -1.f), 1.f));
        b.x = __float2bfloat16(fminf(fmaxf(rintf(wv.z / s), -1.f), 1.f));
        b.y = __float2bfloat16(fminf(fmaxf(rintf(wv.w / s), -1.f), 1.f));
        ((__nv_bfloat162*)g_wq)[2 * i] = a;
        ((__nv_bfloat162*)g_wq)[2 * i + 1] = b;
    }
}

// ---- kernel 3: RMSNorm -> SiLU -> hi/lo bf16 split ----
__global__ void __launch_bounds__(256) act_kernel(const float* __restrict__ xin, int first) {
    const float* in = first ? xin : (const float*)g_y;
    int row = blockIdx.x, t = threadIdx.x;
    const float4* rp = (const float4*)(in + (size_t)row * D_MODEL);
    float4 v[4]; float ss = 0.f;
#pragma unroll
    for (int i = 0; i < 4; i++) {
        v[i] = rp[t + (i << 8)];
        ss += v[i].x * v[i].x + v[i].y * v[i].y + v[i].z * v[i].z + v[i].w * v[i].w;
    }
    __shared__ float red[256];
    red[t] = ss; __syncthreads();
#pragma unroll
    for (int o = 128; o > 0; o >>= 1) { if (t < o) red[t] += red[t + o]; __syncthreads(); }
    float rs = rsqrtf(red[0] * (1.0f / 4096.0f) + 1.1920929e-7f);
    __nv_bfloat162* hi = (__nv_bfloat162*)(g_ahi + (size_t)row * D_MODEL);
    __nv_bfloat162* lo = (__nv_bfloat162*)(g_alo + (size_t)row * D_MODEL);
#pragma unroll
    for (int i = 0; i < 4; i++) {
        float h[4] = {v[i].x * rs, v[i].y * rs, v[i].z * rs, v[i].w * rs};
        __nv_bfloat16 hh[4]; float ll[4];
#pragma unroll
        for (int e = 0; e < 4; e++) {
            h[e] = h[e] / (1.0f + expf(-h[e]));
            hh[e] = __float2bfloat16(h[e]);
            ll[e] = h[e] - __bfloat162float(hh[e]);
        }
        int base = (t + (i << 8)) * 2;
        __nv_bfloat162 p0, p1, q0, q1;
        p0.x = hh[0]; p0.y = hh[1]; p1.x = hh[2]; p1.y = hh[3];
        q0.x = __float2bfloat16(ll[0]); q0.y = __float2bfloat16(ll[1]);
        q1.x = __float2bfloat16(ll[2]); q1.y = __float2bfloat16(ll[3]);
        hi[base] = p0; hi[base + 1] = p1;
        lo[base] = q0; lo[base + 1] = q1;
    }
}

// ---- kernel 4: GEMM y = Ahi@Wq^T + Alo@Wq^T ----
#define STAGES 4
#define STAGE_BYTES 49152u
#define SMEM_TOTAL (2048 + STAGES * 49152)

#if defined(__CUDA_ARCH_FEAT_SM103_ALL) || defined(__CUDA_ARCH_FEAT_SM100_ALL)
#define HAVE_TCGEN05 1
#else
#define HAVE_TCGEN05 0
#endif

#if !HAVE_TCGEN05 || !defined(__CUDA_ARCH__)
// mma.sync helpers (baseline PTX, legal on plain sm_103)
static __device__ __forceinline__ void ldsm4(uint32_t a[4], uint32_t addr) {
    asm volatile("ldmatrix.sync.aligned.m8n8.x4.shared.b16 {%0,%1,%2,%3}, [%4];"
                 : "=r"(a[0]), "=r"(a[1]), "=r"(a[2]), "=r"(a[3]) : "r"(addr));
}
static __device__ __forceinline__ void mma16816(float c[4], const uint32_t a[4], const uint32_t* b) {
    asm volatile("mma.sync.aligned.m16n8k16.row.col.f32.bf16.bf16.f32 "
                 "{%0,%1,%2,%3}, {%4,%5,%6,%7}, {%8,%9}, {%0,%1,%2,%3};"
                 : "+f"(c[0]), "+f"(c[1]), "+f"(c[2]), "+f"(c[3])
                 : "r"(a[0]), "r"(a[1]), "r"(a[2]), "r"(a[3]), "r"(b[0]), "r"(b[1]));
}
#endif

#if HAVE_TCGEN05
#define MBAR_INIT(a, c) asm volatile("mbarrier.init.shared.b64 [%0], %1;" :: "r"((uint32_t)(a)), "r"((uint32_t)(c)) : "memory")
#define MBAR_WAIT(a, ph) do { \
    asm volatile("{\n\t.reg .pred P1;\n\tW%=:\n\t" \
        "mbarrier.try_wait.parity.acquire.cta.shared::cta.b64 P1, [%0], %1, 0x989680;\n\t" \
        "@P1 bra.uni D%=;\n\tbra.uni W%=;\n\tD%=:\n\t}" \
        :: "r"((uint32_t)(a)), "r"((uint32_t)(ph)) : "memory"); } while (0)
#define TC_COMMIT(mbar) asm volatile("tcgen05.commit.cta_group::1.mbarrier::arrive::one.shared::cluster.b64 [%0];" :: "r"((uint32_t)(mbar)) : "memory")
#define TC_LD32(r, ta) asm volatile( \
    "tcgen05.ld.sync.aligned.32x32b.x32.b32 " \
    "{%0,%1,%2,%3,%4,%5,%6,%7,%8,%9,%10,%11,%12,%13,%14,%15," \
    "%16,%17,%18,%19,%20,%21,%22,%23,%24,%25,%26,%27,%28,%29,%30,%31}, [%32];" \
    : "=r"((r)[0]),"=r"((r)[1]),"=r"((r)[2]),"=r"((r)[3]),"=r"((r)[4]),"=r"((r)[5]),"=r"((r)[6]),"=r"((r)[7]), \
      "=r"((r)[8]),"=r"((r)[9]),"=r"((r)[10]),"=r"((r)[11]),"=r"((r)[12]),"=r"((r)[13]),"=r"((r)[14]),"=r"((r)[15]), \
      "=r"((r)[16]),"=r"((r)[17]),"=r"((r)[18]),"=r"((r)[19]),"=r"((r)[20]),"=r"((r)[21]),"=r"((r)[22]),"=r"((r)[23]), \
      "=r"((r)[24]),"=r"((r)[25]),"=r"((r)[26]),"=r"((r)[27]),"=r"((r)[28]),"=r"((r)[29]),"=r"((r)[30]),"=r"((r)[31]) \
    : "r"(ta))
static __device__ __forceinline__ uint64_t sw128_desc(uint32_t addr) {
    const uint64_t BASE = (2ull << 61) | (1ull << 46) | (64ull << 32) | (1ull << 16);
    return BASE | (uint64_t)((addr >> 4) & 0x3FFFu);
}
static __device__ __forceinline__ void mma_f16_ss(uint32_t d, uint64_t a, uint64_t b,
                                                  uint32_t idesc, uint32_t en) {
    asm volatile("{\n\t.reg .pred p;\n\tsetp.ne.u32 p, %5, 0;\n\t"
        "tcgen05.mma.cta_group::1.kind::f16 [%0], %1, %2, %3, {%4,%4,%4,%4}, p;\n\t}"
        :: "r"(d), "l"(a), "l"(b), "r"(idesc), "r"(0u), "r"(en) : "memory");
}
static constexpr uint32_t IDESC = (1u << 4) | (1u << 7) | (1u << 10) | (16u << 17) | (8u << 24);
#endif

__global__ void __launch_bounds__(256, 1) gemm_kernel(int last, float* __restrict__ dout) {
    extern __shared__ char smraw[];
    uint32_t sb = smem_u32(smraw);
    uint32_t ab = (sb + 1023u) & ~1023u;
    uint32_t stg = ab + 1024;
    float* __restrict__ out = last ? dout : g_y;

    int tid = threadIdx.x, bid = blockIdx.x;
    int group = bid >> 8, rem = bid & 255;
    int m0 = ((group << 3) + (rem & 7)) << 7;
    int n0 = (rem >> 3) << 7;

    uint32_t soff[4]; size_t aofs[4], bofs[4];
#pragma unroll
    for (int i = 0; i < 4; i++) {
        int q = tid + (i << 8), r = q >> 3, c = q & 7;
        uint32_t bo = (uint32_t)(r * 128 + c * 16);
        soff[i] = bo ^ ((bo >> 3) & 0x70);
        aofs[i] = (size_t)(m0 + r) * D_MODEL + c * 8;
        bofs[i] = (size_t)(n0 + r) * D_MODEL + c * 8;
    }
#define LOAD_STAGE(s_, kt_) do { \
    uint32_t st_ = stg + (uint32_t)(s_) * STAGE_BYTES; \
    size_t k0_ = (size_t)(kt_) * 64; \
    _Pragma("unroll") \
    for (int i_ = 0; i_ < 4; i_++) { \
        CP16(st_ + soff[i_],          g_ahi + aofs[i_] + k0_); \
        CP16(st_ + 16384u + soff[i_], g_alo + aofs[i_] + k0_); \
        CP16(st_ + 32768u + soff[i_], g_wq  + bofs[i_] + k0_); \
    } } while (0)

    const int KT = D_MODEL / 64;

#if HAVE_TCGEN05
    uint32_t tptr = ab, mb = ab + 8;
    if (tid < 32) {
        asm volatile("tcgen05.alloc.cta_group::1.sync.aligned.shared::cta.b32 [%0], %1;"
                     :: "r"(tptr), "r"(128) : "memory");
        asm volatile("tcgen05.relinquish_alloc_permit.cta_group::1.sync.aligned;");
    }
    if (tid == 0) for (int s = 0; s < 5; s++) MBAR_INIT(mb + 8 * s, 1);
    __syncthreads();
    uint32_t tmem;
    asm volatile("ld.shared.b32 %0, [%1];" : "=r"(tmem) : "r"(tptr));

    int ph[4] = {0, 0, 0, 0};
    for (int j = 0; j < STAGES - 1; j++) { LOAD_STAGE(j, j); CP_COMMIT(); }
    for (int j = 0; j < KT; j++) {
        int s = j & 3;
        CP_WAIT(2);
        __syncthreads();
        if (tid == 0) {
            asm volatile("fence.proxy.async.shared::cta;" ::: "memory");
            uint32_t st = stg + (uint32_t)s * STAGE_BYTES;
            uint64_t ad = sw128_desc(st), ld = sw128_desc(st + 16384u), bd = sw128_desc(st + 32768u);
#pragma unroll
            for (int ks = 0; ks < 4; ks++)
                mma_f16_ss(tmem, ad + 2 * ks, bd + 2 * ks, IDESC, (j == 0 && ks == 0) ? 0u : 1u);
#pragma unroll
            for (int ks = 0; ks < 4; ks++)
                mma_f16_ss(tmem, ld + 2 * ks, bd + 2 * ks, IDESC, 1u);
            TC_COMMIT(mb + 8 * s);
        }
        int jn = j + STAGES - 1;
        if (jn < KT) {
            int sn = jn & 3;
            if (j >= 1) { MBAR_WAIT(mb + 8 * sn, ph[sn]); ph[sn] ^= 1; }
            LOAD_STAGE(sn, jn);
        }
        CP_COMMIT();
    }
    CP_WAIT(0);
    __syncthreads();
    if (tid == 0) TC_COMMIT(mb + 32);
    MBAR_WAIT(mb + 32, 0);
    asm volatile("tcgen05.fence::after_thread_sync;" ::: "memory");
    int wid = tid >> 5, lane = tid & 31;
    if (wid < 4) {
        float4* orow = (float4*)(out + (size_t)(m0 + wid * 32 + lane) * D_MODEL + n0);
#pragma unroll
        for (int cc = 0; cc < 4; cc++) {
            uint32_t r[32];
            TC_LD32(r, tmem + cc * 32);
            asm volatile("tcgen05.wait::ld.sync.aligned;" ::: "memory");
#pragma unroll
            for (int v = 0; v < 8; v++)
                orow[cc * 8 + v] = make_float4(__uint_as_float(r[4 * v]), __uint_as_float(r[4 * v + 1]),
                                               __uint_as_float(r[4 * v + 2]), __uint_as_float(r[4 * v + 3]));
        }
    }
    __syncthreads();
    if (tid < 32)
        asm volatile("tcgen05.dealloc.cta_group::1.sync.aligned.b32 %0, %1;" :: "r"(tmem), "r"(128));
#else
    // ---------- mma.sync fallback: 8 warps, 64x32 warp tiles ----------
    int wid = tid >> 5, lane = tid & 31;
    int wm = (wid & 1) * 64;       // warp M offset in CTA tile
    int wn = (wid >> 1) * 32;      // warp N offset
    float acc[4][4][4];
#pragma unroll
    for (int a = 0; a < 4; a++)
#pragma unroll
        for (int b = 0; b < 4; b++)
#pragma unroll
            for (int c = 0; c < 4; c++) acc[a][b][c] = 0.f;

    // precompute per-lane ldmatrix bases (row*128 and xor mask (row&7)<<4)
    uint32_t aRow[4], aX[4], bRow[2], bX[2];
    uint32_t koffA = ((lane >> 4) & 1) * 16;          // A k-chunk byte offset
    uint32_t koffB = ((lane >> 3) & 1) * 16;          // B k-chunk byte offset
#pragma unroll
    for (int mt = 0; mt < 4; mt++) {
        uint32_t row = wm + mt * 16 + (lane & 15);
        aRow[mt] = row * 128u;
        aX[mt] = (row & 7u) << 4;
    }
#pragma unroll
    for (int p = 0; p < 2; p++) {
        uint32_t row = wn + p * 16 + ((lane >> 4) * 8) + (lane & 7);
        bRow[p] = row * 128u;
        bX[p] = (row & 7u) << 4;
    }

    for (int j = 0; j < STAGES - 1; j++) { LOAD_STAGE(j, j); CP_COMMIT(); }

    for (int j = 0; j < KT; j++) {
        int s = j & 3;
        CP_WAIT(2);
        __syncthreads();
        uint32_t hiB = stg + (uint32_t)s * STAGE_BYTES;
        uint32_t loB = hiB + 16384u;
        uint32_t wqB = hiB + 32768u;
#pragma unroll
        for (int kk = 0; kk < 4; kk++) {
            uint32_t kb = kk * 32u;   // kk*16 elems * 2B
            uint32_t bfr[2][4];
#pragma unroll
            for (int p = 0; p < 2; p++)
                ldsm4(bfr[p], wqB + bRow[p] + ((kb + koffB) ^ bX[p]));
#pragma unroll
            for (int mt = 0; mt < 4; mt++) {
                uint32_t afr[4];
                ldsm4(afr, hiB + aRow[mt] + ((kb + koffA) ^ aX[mt]));
#pragma unroll
                for (int nt = 0; nt < 4; nt++)
                    mma16816(acc[mt][nt], afr, &bfr[nt >> 1][(nt & 1) * 2]);
            }
#pragma unroll
            for (int mt = 0; mt < 4; mt++) {
                uint32_t afr[4];
                ldsm4(afr, loB + aRow[mt] + ((kb + koffA) ^ aX[mt]));
#pragma unroll
                for (int nt = 0; nt < 4; nt++)
                    mma16816(acc[mt][nt], afr, &bfr[nt >> 1][(nt & 1) * 2]);
            }
        }
        __syncthreads();
        int jn = j + STAGES - 1;
        if (jn < KT) { int sn = jn & 3; LOAD_STAGE(sn, jn); }
        CP_COMMIT();
    }
    CP_WAIT(0);

    int g = lane >> 2, t4 = lane & 3;
#pragma unroll
    for (int mt = 0; mt < 4; mt++) {
        size_t r0 = (size_t)(m0 + wm + mt * 16 + g);
#pragma unroll
        for (int nt = 0; nt < 4; nt++) {
            int col = n0 + wn + nt * 8 + t4 * 2;
            float2* p0 = (float2*)(out + r0 * D_MODEL + col);
            float2* p1 = (float2*)(out + (r0 + 8) * D_MODEL + col);
            *p0 = make_float2(acc[mt][nt][0], acc[mt][nt][1]);
            *p1 = make_float2(acc[mt][nt][2], acc[mt][nt][3]);
        }
    }
#endif
}

extern "C" void kernel_launch(void* const* d_in, const int* in_sizes, int n_in,
                              void* d_out, int out_size) {
    const float* x = (const float*)d_in[0];
    const float* w[3] = {(const float*)d_in[1], (const float*)d_in[2], (const float*)d_in[3]};
    cudaFuncSetAttribute(gemm_kernel, cudaFuncAttributeMaxDynamicSharedMemorySize, SMEM_TOTAL);
    for (int l = 0; l < 3; l++) {
        absmean_part<<<1024, 256>>>(w[l]);
        absmean_fin<<<1, 256>>>();
        quant_kernel<<<2048, 256>>>(w[l]);
        act_kernel<<<N_TOK, 256>>>(x, l == 0);
        gemm_kernel<<<2048, 256, SMEM_TOTAL>>>(l == 2, (float*)d_out);
    }
}